// round 5
// baseline (speedup 1.0000x reference)
#include <cuda_runtime.h>
#include <math.h>

// ---------------------------------------------------------------------------
// CFNO folded: patchify(16x16) -> FFT(256) -> complex linear -> IFFT(16).real
// -> 1x1 conv == y = p @ G + g0 with real G[256][16]; then GroupNorm(8,16).
//
// Main kernel: 4 threads per patch (lane quarter), fully-coalesced LDG.128,
// XOR-swizzled G in smem (conflict-free quarter loads), fp32x2 FMA pipe,
// shfl butterfly combine, smem-staged coalesced output.
// ---------------------------------------------------------------------------

#define PI_D 3.141592653589793238462643383279502884

__device__ float g_G[4096];               // [256][16]
__device__ float g_g0[16];
__device__ float g_Y[8 * 16 * 128 * 128]; // 8 MB, (b,e,h,w)
__device__ float g_psum[64 * 256];        // [b*8+g][block-in-batch]
__device__ float g_psq[64 * 256];
__device__ float g_mean[64];
__device__ float g_istd[64];

// ---- packed fp32x2 helpers ----
__device__ __forceinline__ unsigned long long pack2s(float a) {
    unsigned long long r;
    asm("mov.b64 %0, {%1, %1};" : "=l"(r) : "f"(a));
    return r;
}
__device__ __forceinline__ void unpack2(unsigned long long v, float& lo, float& hi) {
    asm("mov.b64 {%0, %1}, %2;" : "=f"(lo), "=f"(hi) : "l"(v));
}
__device__ __forceinline__ void fma2(unsigned long long& acc,
                                     unsigned long long a, unsigned long long b) {
    asm("fma.rn.f32x2 %0, %1, %2, %0;" : "+l"(acc) : "l"(a), "l"(b));
}

// ---------------------------------------------------------------------------
// Kernel 1: fold FFT + complex linear + IFFT.real + conv into G, g0.
// ---------------------------------------------------------------------------
__global__ void precompute_kernel(const float* __restrict__ wr, const float* __restrict__ wi,
                                  const float* __restrict__ br, const float* __restrict__ bi,
                                  const float* __restrict__ cw, const float* __restrict__ cb) {
    __shared__ float cosT[256], sinT[256];
    __shared__ float swr[16 * 257], swi[16 * 257];
    __shared__ float sCR[256], sCI[256];
    __shared__ float sMR[256], sMI[256];
    const int tid = threadIdx.x;

    {
        double s, c;
        sincos(2.0 * PI_D * (double)tid / 256.0, &s, &c);
        cosT[tid] = (float)c; sinT[tid] = (float)s;
    }
    for (int i = tid; i < 4096; i += 256) {
        int d = i >> 8, k = i & 255;
        swr[d * 257 + k] = wr[i];
        swi[d * 257 + k] = wi[i];
    }
    __syncthreads();

    const int hi4 = tid >> 4, lo4 = tid & 15;
    {   // CR/CI: d = hi4, e = lo4
        float cr = 0.f, ci = 0.f;
#pragma unroll
        for (int m = 0; m < 16; m++) {
            int t = ((hi4 * m) & 15) << 4;
            float w = cw[lo4 * 16 + m];
            cr += w * cosT[t];
            ci += w * sinT[t];
        }
        sCR[hi4 * 16 + lo4] = cr; sCI[hi4 * 16 + lo4] = ci;
    }
    {   // MR/MI: jl = hi4, d = lo4; 4-way split accumulator chains
        const int jl = hi4, d = lo4;
        const int j = (blockIdx.x << 4) + jl;
        const float* a  = swr + d * 257;
        const float* bb = swi + d * 257;
        float mr0 = 0.f, mi0 = 0.f, mr1 = 0.f, mi1 = 0.f;
        float mr2 = 0.f, mi2 = 0.f, mr3 = 0.f, mi3 = 0.f;
        for (int k = 0; k < 256; k += 4) {
            int t0 = (k * j) & 255, t1 = (t0 + j) & 255;
            int t2 = (t1 + j) & 255, t3 = (t2 + j) & 255;
            float c0 = cosT[t0], s0 = sinT[t0], a0 = a[k],     b0 = bb[k];
            float c1 = cosT[t1], s1 = sinT[t1], a1 = a[k + 1], b1 = bb[k + 1];
            float c2 = cosT[t2], s2 = sinT[t2], a2 = a[k + 2], b2 = bb[k + 2];
            float c3 = cosT[t3], s3 = sinT[t3], a3 = a[k + 3], b3 = bb[k + 3];
            mr0 += a0 * c0 + b0 * s0;  mi0 += b0 * c0 - a0 * s0;
            mr1 += a1 * c1 + b1 * s1;  mi1 += b1 * c1 - a1 * s1;
            mr2 += a2 * c2 + b2 * s2;  mi2 += b2 * c2 - a2 * s2;
            mr3 += a3 * c3 + b3 * s3;  mi3 += b3 * c3 - a3 * s3;
        }
        sMR[jl * 16 + d] = (mr0 + mr1) + (mr2 + mr3);
        sMI[jl * 16 + d] = (mi0 + mi1) + (mi2 + mi3);
    }
    __syncthreads();
    {   // G[j][e]
        const int jl = hi4, e = lo4;
        const int j = (blockIdx.x << 4) + jl;
        float g = 0.f;
#pragma unroll
        for (int d = 0; d < 16; d++)
            g += sMR[jl * 16 + d] * sCR[d * 16 + e] - sMI[jl * 16 + d] * sCI[d * 16 + e];
        g_G[j * 16 + e] = g * (1.0f / 64.0f);
    }
    if (blockIdx.x == 0 && tid < 16) {
        float acc = cb[tid];
        for (int m = 0; m < 16; m++) {
            float b0 = 0.f;
            for (int d = 0; d < 16; d++) {
                int t = ((d * m) & 15) << 4;
                b0 += br[d] * cosT[t] - bi[d] * sinT[t];
            }
            acc += cw[tid * 16 + m] * b0 * 0.25f;
        }
        g_g0[tid] = acc;
    }
}

// ---------------------------------------------------------------------------
// Kernel 2 (hot): 2048 blocks x 256 threads. Thread = one patch-quarter:
// patch P = blk*64 + tid/4, quarter q = tid&3 (s2 in [4q, 4q+4)).
// Warp LDG.128 covers 512B contiguous (perfect coalescing). G slice loads
// from smem use XOR-swizzled e-chunk layout: for fixed (s1,j,c), the 4
// distinct quarter addresses land in 4 distinct 16B bank-quads.
// ---------------------------------------------------------------------------
__global__ void __launch_bounds__(256) main_kernel(const float* __restrict__ x) {
    __shared__ __align__(16) float sG[4096];
    __shared__ float sg0[16];
    __shared__ float sY[16 * 65];
    __shared__ float sred[8][16];
    const int tid = threadIdx.x;

    {   // load G swizzled: row r, logical e-chunk c -> physical slot c ^ ((r>>2)&3)
        const float4* g4 = (const float4*)g_G;
        float4* s4 = (float4*)sG;
        for (int i = tid; i < 1024; i += 256) {
            int r = i >> 2, c = i & 3;
            s4[(r << 2) + (c ^ ((r >> 2) & 3))] = g4[i];
        }
        if (tid < 16) sg0[tid] = g_g0[tid];
    }
    __syncthreads();

    const int P  = (blockIdx.x << 6) + (tid >> 2);   // global patch id
    const int q  = tid & 3;                           // quarter
    const int b  = P >> 14;
    const int hr = (P >> 7) & 127;                    // patch row
    const int w  = P & 127;                           // patch col
    const float* xp = x + (((size_t)b) << 22) + ((size_t)hr << 15) + (w << 4) + (q << 2);

    // 4 precomputed smem pointers: logical chunk c lives at q*256B + (c^q)*16B
    const char* gq = (const char*)sG + (q << 8);
    const ulonglong2* gptr[4];
#pragma unroll
    for (int c = 0; c < 4; c++)
        gptr[c] = (const ulonglong2*)(gq + ((c ^ q) << 4));

    unsigned long long acc[8];
#pragma unroll
    for (int i = 0; i < 8; i++) acc[i] = 0ull;

    float4 buf = *(const float4*)xp;
#pragma unroll
    for (int s1 = 0; s1 < 16; s1++) {
        float4 cur = buf;
        if (s1 < 15) buf = *(const float4*)(xp + ((s1 + 1) << 11));
        float xv[4] = {cur.x, cur.y, cur.z, cur.w};
#pragma unroll
        for (int j = 0; j < 4; j++) {
            unsigned long long v = pack2s(xv[j]);
            const int base = (s1 << 6) + (j << 2);    // in 16B units
#pragma unroll
            for (int c = 0; c < 4; c++) {
                ulonglong2 g = gptr[c][base];
                fma2(acc[2 * c],     v, g.x);
                fma2(acc[2 * c + 1], v, g.y);
            }
        }
    }

    float y[16];
#pragma unroll
    for (int i = 0; i < 8; i++) unpack2(acc[i], y[2 * i], y[2 * i + 1]);

    // butterfly: combine 4 quarter-partials (lanes q=0..3 of each patch group)
#pragma unroll
    for (int e = 0; e < 16; e++) {
        y[e] += __shfl_xor_sync(0xffffffffu, y[e], 1);
        y[e] += __shfl_xor_sync(0xffffffffu, y[e], 2);
    }
#pragma unroll
    for (int e = 0; e < 16; e++) y[e] += sg0[e];

    // stage quarter e-range to smem (each lane writes its 4 e's, no duplication)
    const int wl = tid >> 2;                           // 0..63 patch within block
#pragma unroll
    for (int i = 0; i < 4; i++) sY[(4 * q + i) * 65 + wl] = y[4 * q + i];

    // GroupNorm partials: truncated butterfly (offsets 16,8,4) sums exactly one
    // lane per 4-lane patch group -> each patch counted ONCE.
    float gs[8], gqv[8];
#pragma unroll
    for (int g = 0; g < 8; g++) {
        float a = y[2 * g], c = y[2 * g + 1];
        gs[g] = a + c;
        gqv[g] = a * a + c * c;
    }
#pragma unroll
    for (int off = 16; off >= 4; off >>= 1) {
#pragma unroll
        for (int g = 0; g < 8; g++) {
            gs[g]  += __shfl_down_sync(0xffffffffu, gs[g], off);
            gqv[g] += __shfl_down_sync(0xffffffffu, gqv[g], off);
        }
    }
    const int lane = tid & 31, wrp = tid >> 5;
    if (lane == 0) {
#pragma unroll
        for (int g = 0; g < 8; g++) { sred[wrp][g] = gs[g]; sred[wrp][8 + g] = gqv[g]; }
    }
    __syncthreads();

    // coalesced g_Y write from staging: thread -> (e = tid>>4, 4 w's)
    {
        const int e = tid >> 4, w4 = (tid & 15) << 2;
        const int w0 = (blockIdx.x & 1) << 6;
        float4 v;
        v.x = sY[e * 65 + w4];     v.y = sY[e * 65 + w4 + 1];
        v.z = sY[e * 65 + w4 + 2]; v.w = sY[e * 65 + w4 + 3];
        *(float4*)&g_Y[(((size_t)(b * 16 + e)) << 14) + (hr << 7) + w0 + w4] = v;
    }

    if (tid < 16) {
        float s = 0.f;
#pragma unroll
        for (int k = 0; k < 8; k++) s += sred[k][tid];
        const int bb = blockIdx.x >> 8, blk = blockIdx.x & 255;
        if (tid < 8) g_psum[(bb * 8 + tid) * 256 + blk] = s;
        else         g_psq[(bb * 8 + tid - 8) * 256 + blk] = s;
    }
}

// ---------------------------------------------------------------------------
// Kernel 3: reduce 256 partials per (batch,group).
// Each patch counted exactly once -> N = 2 channels * 128 * 128 = 32768.
// ---------------------------------------------------------------------------
__global__ void stats_kernel() {
    const int tid = threadIdx.x;          // 512
    const int bg = tid >> 3, k = tid & 7;
    float s = 0.f, q = 0.f;
#pragma unroll
    for (int i = 0; i < 32; i++) {
        s += g_psum[bg * 256 + (i << 3) + k];
        q += g_psq[bg * 256 + (i << 3) + k];
    }
#pragma unroll
    for (int off = 4; off; off >>= 1) {
        s += __shfl_down_sync(0xffffffffu, s, off, 8);
        q += __shfl_down_sync(0xffffffffu, q, off, 8);
    }
    if (k == 0) {
        const float invN = 1.0f / 32768.0f;
        float mean = s * invN;
        float var  = q * invN - mean * mean;
        g_mean[bg] = mean;
        g_istd[bg] = rsqrtf(var + 1e-5f);
    }
}

// ---------------------------------------------------------------------------
// Kernel 4: normalize + affine.
// ---------------------------------------------------------------------------
__global__ void __launch_bounds__(256) finalize_kernel(const float* __restrict__ gamma,
                                                       const float* __restrict__ beta,
                                                       float* __restrict__ out) {
    const int t = blockIdx.x * blockDim.x + threadIdx.x;   // 262144 threads
#pragma unroll
    for (int r = 0; r < 2; r++) {
        const int idx = t + (r << 18);
        float4 v = ((const float4*)g_Y)[idx];
        const int plane = idx >> 12;
        const int e = plane & 15, b = plane >> 4;
        const int bg = b * 8 + (e >> 1);
        const float is = g_istd[bg];
        const float sc = is * gamma[e];
        const float sh = beta[e] - g_mean[bg] * sc;
        v.x = v.x * sc + sh; v.y = v.y * sc + sh;
        v.z = v.z * sc + sh; v.w = v.w * sc + sh;
        ((float4*)out)[idx] = v;
    }
}

extern "C" void kernel_launch(void* const* d_in, const int* in_sizes, int n_in,
                              void* d_out, int out_size) {
    const float* x     = (const float*)d_in[0];
    const float* wr    = (const float*)d_in[1];
    const float* wi    = (const float*)d_in[2];
    const float* br    = (const float*)d_in[3];
    const float* bi    = (const float*)d_in[4];
    const float* cw    = (const float*)d_in[5];
    const float* cb    = (const float*)d_in[6];
    const float* gamma = (const float*)d_in[7];
    const float* beta  = (const float*)d_in[8];
    float* out = (float*)d_out;

    precompute_kernel<<<16, 256>>>(wr, wi, br, bi, cw, cb);
    main_kernel<<<2048, 256>>>(x);
    stats_kernel<<<1, 512>>>();
    finalize_kernel<<<1024, 256>>>(gamma, beta, out);
}

// round 6
// speedup vs baseline: 1.3978x; 1.3978x over previous
#include <cuda_runtime.h>
#include <math.h>

// ---------------------------------------------------------------------------
// CFNO folded: patchify(16x16) -> FFT(256) -> complex linear -> IFFT(16).real
// -> 1x1 conv == y = p @ G + g0 with real G[256][16]; then GroupNorm(8,16).
//
// Main kernel: full patch per thread. x staged via cp.async at 80B/patch
// pitch (conflict-free LDS.128 reads, coprime-5 bank walk). G broadcast
// (warp-uniform) from smem. 3-stage pipeline, 1 barrier/iter. fp32x2 FMAs.
// ---------------------------------------------------------------------------

#define PI_D 3.141592653589793238462643383279502884

__device__ float g_G[4096];               // [256][16]
__device__ float g_g0[16];
__device__ float g_Y[8 * 16 * 128 * 128]; // 8 MB, (b,e,h,w)
__device__ float g_psum[64 * 128];        // [b*8+g][block-in-batch]
__device__ float g_psq[64 * 128];
__device__ float g_mean[64];
__device__ float g_istd[64];

// ---- packed fp32x2 helpers ----
__device__ __forceinline__ unsigned long long pack2s(float a) {
    unsigned long long r;
    asm("mov.b64 %0, {%1, %1};" : "=l"(r) : "f"(a));
    return r;
}
__device__ __forceinline__ void unpack2(unsigned long long v, float& lo, float& hi) {
    asm("mov.b64 {%0, %1}, %2;" : "=f"(lo), "=f"(hi) : "l"(v));
}
__device__ __forceinline__ void fma2(unsigned long long& acc,
                                     unsigned long long a, unsigned long long b) {
    asm("fma.rn.f32x2 %0, %1, %2, %0;" : "+l"(acc) : "l"(a), "l"(b));
}
__device__ __forceinline__ void cp_async16(const void* smem_dst, const void* gmem_src) {
    unsigned d;
    asm("{ .reg .u64 t; cvta.to.shared.u64 t, %1; cvt.u32.u64 %0, t; }"
        : "=r"(d) : "l"(smem_dst));
    asm volatile("cp.async.cg.shared.global [%0], [%1], 16;" :: "r"(d), "l"(gmem_src));
}

// ---------------------------------------------------------------------------
// Kernel 1: fold FFT + complex linear + IFFT.real + conv into G, g0.
// ---------------------------------------------------------------------------
__global__ void precompute_kernel(const float* __restrict__ wr, const float* __restrict__ wi,
                                  const float* __restrict__ br, const float* __restrict__ bi,
                                  const float* __restrict__ cw, const float* __restrict__ cb) {
    __shared__ float cosT[256], sinT[256];
    __shared__ float swr[16 * 257], swi[16 * 257];
    __shared__ float sCR[256], sCI[256];
    __shared__ float sMR[256], sMI[256];
    const int tid = threadIdx.x;

    {
        double s, c;
        sincos(2.0 * PI_D * (double)tid / 256.0, &s, &c);
        cosT[tid] = (float)c; sinT[tid] = (float)s;
    }
    for (int i = tid; i < 4096; i += 256) {
        int d = i >> 8, k = i & 255;
        swr[d * 257 + k] = wr[i];
        swi[d * 257 + k] = wi[i];
    }
    __syncthreads();

    const int hi4 = tid >> 4, lo4 = tid & 15;
    {   // CR/CI: d = hi4, e = lo4
        float cr = 0.f, ci = 0.f;
#pragma unroll
        for (int m = 0; m < 16; m++) {
            int t = ((hi4 * m) & 15) << 4;
            float w = cw[lo4 * 16 + m];
            cr += w * cosT[t];
            ci += w * sinT[t];
        }
        sCR[hi4 * 16 + lo4] = cr; sCI[hi4 * 16 + lo4] = ci;
    }
    {   // MR/MI: jl = hi4, d = lo4
        const int jl = hi4, d = lo4;
        const int j = (blockIdx.x << 4) + jl;
        const float* a  = swr + d * 257;
        const float* bb = swi + d * 257;
        float mr0 = 0.f, mi0 = 0.f, mr1 = 0.f, mi1 = 0.f;
        float mr2 = 0.f, mi2 = 0.f, mr3 = 0.f, mi3 = 0.f;
        for (int k = 0; k < 256; k += 4) {
            int t0 = (k * j) & 255, t1 = (t0 + j) & 255;
            int t2 = (t1 + j) & 255, t3 = (t2 + j) & 255;
            float c0 = cosT[t0], s0 = sinT[t0], a0 = a[k],     b0 = bb[k];
            float c1 = cosT[t1], s1 = sinT[t1], a1 = a[k + 1], b1 = bb[k + 1];
            float c2 = cosT[t2], s2 = sinT[t2], a2 = a[k + 2], b2 = bb[k + 2];
            float c3 = cosT[t3], s3 = sinT[t3], a3 = a[k + 3], b3 = bb[k + 3];
            mr0 += a0 * c0 + b0 * s0;  mi0 += b0 * c0 - a0 * s0;
            mr1 += a1 * c1 + b1 * s1;  mi1 += b1 * c1 - a1 * s1;
            mr2 += a2 * c2 + b2 * s2;  mi2 += b2 * c2 - a2 * s2;
            mr3 += a3 * c3 + b3 * s3;  mi3 += b3 * c3 - a3 * s3;
        }
        sMR[jl * 16 + d] = (mr0 + mr1) + (mr2 + mr3);
        sMI[jl * 16 + d] = (mi0 + mi1) + (mi2 + mi3);
    }
    __syncthreads();
    {   // G[j][e]
        const int jl = hi4, e = lo4;
        const int j = (blockIdx.x << 4) + jl;
        float g = 0.f;
#pragma unroll
        for (int d = 0; d < 16; d++)
            g += sMR[jl * 16 + d] * sCR[d * 16 + e] - sMI[jl * 16 + d] * sCI[d * 16 + e];
        g_G[j * 16 + e] = g * (1.0f / 64.0f);
    }
    if (blockIdx.x == 0 && tid < 16) {
        float acc = cb[tid];
        for (int m = 0; m < 16; m++) {
            float b0 = 0.f;
            for (int d = 0; d < 16; d++) {
                int t = ((d * m) & 15) << 4;
                b0 += br[d] * cosT[t] - bi[d] * sinT[t];
            }
            acc += cw[tid * 16 + m] * b0 * 0.25f;
        }
        g_g0[tid] = acc;
    }
}

// ---------------------------------------------------------------------------
// Kernel 2 (hot): grid 1024 x 128 threads. Block = one patch row (128
// patches, batch b = bid>>7, row hr = bid&127); thread owns patch w = tid.
// Per s1 step, one image row (8KB) is staged via cp.async into a 3-deep
// pipeline with 80B/patch pitch. Compute: 4 conflict-free LDS.128 (own x)
// + 64 warp-uniform broadcast LDS.128 (G) + 128 fma2 per warp.
// ---------------------------------------------------------------------------
#define STAGE_BYTES (128 * 80)   // 10240

__global__ void __launch_bounds__(128) main_kernel(const float* __restrict__ x) {
    __shared__ __align__(16) char sStage[3][STAGE_BYTES];  // 30720
    __shared__ __align__(16) float sG[4096];               // 16384
    __shared__ float sg0[16];
    __shared__ float sred[4][16];
    const int tid = threadIdx.x;
    const int b  = blockIdx.x >> 7;
    const int hr = blockIdx.x & 127;

    {   // G + bias into smem
        const float4* g4 = (const float4*)g_G;
        float4* s4 = (float4*)sG;
#pragma unroll
        for (int u = 0; u < 8; u++) s4[tid + (u << 7)] = g4[tid + (u << 7)];
        if (tid < 16) sg0[tid] = g_g0[tid];
    }

    const float* xbase = x + (((size_t)b) << 22) + (((size_t)hr) << 15);

    char* stA = sStage[0];
    char* stB = sStage[1];
    char* stC = sStage[2];

    // prime stages 0,1
#pragma unroll
    for (int u = 0; u < 4; u++) {
        int i = tid + (u << 7), w = i >> 2, q = i & 3;
        cp_async16(stA + w * 80 + (q << 4), xbase + (i << 2));
    }
    asm volatile("cp.async.commit_group;");
#pragma unroll
    for (int u = 0; u < 4; u++) {
        int i = tid + (u << 7), w = i >> 2, q = i & 3;
        cp_async16(stB + w * 80 + (q << 4), xbase + 2048 + (i << 2));
    }
    asm volatile("cp.async.commit_group;");

    unsigned long long acc[8];
#pragma unroll
    for (int i = 0; i < 8; i++) acc[i] = 0ull;

    for (int s1 = 0; s1 < 16; s1++) {
        asm volatile("cp.async.wait_group 1;" ::: "memory");
        __syncthreads();          // stage for s1 ready & visible; s1-1 fully consumed

        if (s1 + 2 < 16) {        // refill the stage freed by compute(s1-1)
            const float* rowp = xbase + ((size_t)(s1 + 2) << 11);
#pragma unroll
            for (int u = 0; u < 4; u++) {
                int i = tid + (u << 7), w = i >> 2, q = i & 3;
                cp_async16(stC + w * 80 + (q << 4), rowp + (i << 2));
            }
        }
        asm volatile("cp.async.commit_group;");   // empty group keeps wait count uniform

        // compute s1 from stA
        const char* st = stA + tid * 80;
#pragma unroll
        for (int q = 0; q < 4; q++) {
            float4 xq = *(const float4*)(st + (q << 4));
            float xv[4] = {xq.x, xq.y, xq.z, xq.w};
#pragma unroll
            for (int j2 = 0; j2 < 4; j2++) {
                unsigned long long v = pack2s(xv[j2]);
                const ulonglong2* gr =
                    (const ulonglong2*)((const char*)sG + (((s1 << 4) + (q << 2) + j2) << 6));
                ulonglong2 gA = gr[0], gB = gr[1];
                fma2(acc[0], v, gA.x); fma2(acc[1], v, gA.y);
                fma2(acc[2], v, gB.x); fma2(acc[3], v, gB.y);
                gA = gr[2]; gB = gr[3];
                fma2(acc[4], v, gA.x); fma2(acc[5], v, gA.y);
                fma2(acc[6], v, gB.x); fma2(acc[7], v, gB.y);
            }
        }
        // rotate stages
        char* t = stA; stA = stB; stB = stC; stC = t;
    }

    // epilogue
    float y[16];
#pragma unroll
    for (int i = 0; i < 8; i++) unpack2(acc[i], y[2 * i], y[2 * i + 1]);
#pragma unroll
    for (int e = 0; e < 16; e++) y[e] += sg0[e];

    // coalesced STG.32 per e (lanes = consecutive w)
    {
        const size_t ybase = (((size_t)(b * 16)) << 14) + (hr << 7) + tid;
#pragma unroll
        for (int e = 0; e < 16; e++) g_Y[ybase + ((size_t)e << 14)] = y[e];
    }

    // GroupNorm partials: each thread = one full patch, counted once.
    float gs[8], gq[8];
#pragma unroll
    for (int g = 0; g < 8; g++) {
        float a = y[2 * g], c = y[2 * g + 1];
        gs[g] = a + c;
        gq[g] = a * a + c * c;
    }
#pragma unroll
    for (int off = 16; off; off >>= 1) {
#pragma unroll
        for (int g = 0; g < 8; g++) {
            gs[g] += __shfl_down_sync(0xffffffffu, gs[g], off);
            gq[g] += __shfl_down_sync(0xffffffffu, gq[g], off);
        }
    }
    const int lane = tid & 31, wrp = tid >> 5;
    if (lane == 0) {
#pragma unroll
        for (int g = 0; g < 8; g++) { sred[wrp][g] = gs[g]; sred[wrp][8 + g] = gq[g]; }
    }
    __syncthreads();
    if (tid < 16) {
        float s = sred[0][tid] + sred[1][tid] + sred[2][tid] + sred[3][tid];
        const int slot = blockIdx.x & 127;
        if (tid < 8) g_psum[(b * 8 + tid) * 128 + slot] = s;
        else         g_psq[(b * 8 + tid - 8) * 128 + slot] = s;
    }
}

// ---------------------------------------------------------------------------
// Kernel 3: reduce 128 partials per (batch,group). N = 2*128*128 = 32768.
// ---------------------------------------------------------------------------
__global__ void stats_kernel() {
    const int tid = threadIdx.x;          // 512
    const int bg = tid >> 3, k = tid & 7;
    float s = 0.f, q = 0.f;
#pragma unroll
    for (int i = 0; i < 16; i++) {
        s += g_psum[bg * 128 + (i << 3) + k];
        q += g_psq[bg * 128 + (i << 3) + k];
    }
#pragma unroll
    for (int off = 4; off; off >>= 1) {
        s += __shfl_down_sync(0xffffffffu, s, off, 8);
        q += __shfl_down_sync(0xffffffffu, q, off, 8);
    }
    if (k == 0) {
        const float invN = 1.0f / 32768.0f;
        float mean = s * invN;
        float var  = q * invN - mean * mean;
        g_mean[bg] = mean;
        g_istd[bg] = rsqrtf(var + 1e-5f);
    }
}

// ---------------------------------------------------------------------------
// Kernel 4: normalize + affine; 8 independent float4 chains per thread.
// ---------------------------------------------------------------------------
__global__ void __launch_bounds__(256) finalize_kernel(const float* __restrict__ gamma,
                                                       const float* __restrict__ beta,
                                                       float* __restrict__ out) {
    const int t = blockIdx.x * blockDim.x + threadIdx.x;   // 65536 threads
#pragma unroll
    for (int r = 0; r < 8; r++) {
        const int idx = t + (r << 16);
        float4 v = ((const float4*)g_Y)[idx];
        const int plane = idx >> 12;          // 4096 float4 per (b,e) plane
        const int e = plane & 15, b = plane >> 4;
        const int bg = b * 8 + (e >> 1);
        const float is = g_istd[bg];
        const float sc = is * gamma[e];
        const float sh = beta[e] - g_mean[bg] * sc;
        v.x = v.x * sc + sh; v.y = v.y * sc + sh;
        v.z = v.z * sc + sh; v.w = v.w * sc + sh;
        ((float4*)out)[idx] = v;
    }
}

extern "C" void kernel_launch(void* const* d_in, const int* in_sizes, int n_in,
                              void* d_out, int out_size) {
    const float* x     = (const float*)d_in[0];
    const float* wr    = (const float*)d_in[1];
    const float* wi    = (const float*)d_in[2];
    const float* br    = (const float*)d_in[3];
    const float* bi    = (const float*)d_in[4];
    const float* cw    = (const float*)d_in[5];
    const float* cb    = (const float*)d_in[6];
    const float* gamma = (const float*)d_in[7];
    const float* beta  = (const float*)d_in[8];
    float* out = (float*)d_out;

    precompute_kernel<<<16, 256>>>(wr, wi, br, bi, cw, cb);
    main_kernel<<<1024, 128>>>(x);
    stats_kernel<<<1, 512>>>();
    finalize_kernel<<<256, 256>>>(gamma, beta, out);
}

// round 10
// speedup vs baseline: 1.5294x; 1.0941x over previous
#include <cuda_runtime.h>
#include <cuda_bf16.h>
#include <math.h>
#include <stdint.h>

// ---------------------------------------------------------------------------
// CFNO folded: patchify(16x16) -> FFT(256) -> complex linear -> IFFT(16).real
// -> 1x1 conv == y = p @ G + g0 (real G[256][16]); then GroupNorm(8,16).
//
// Main kernel: classic HMMA (mma.sync.m16n8k16 bf16) with exact hi/lo split:
//   x = hi + lo (hi = fp32 top-16 bits, exact bf16; lo = x - hi, exact fp32)
//   y = Ah*Bh + Al*Bh + Ah*Bl   (each product exact in fp32; AlBl ~2^-16 dropped)
// A loaded gmem -> registers directly in fragment layout (no smem staging).
// ---------------------------------------------------------------------------

#define PI_D 3.141592653589793238462643383279502884

__device__ float g_B[4096];               // [256 k][16 e] folded matrix (fp32)
__device__ float g_g0[16];
__device__ uint2 g_Bfh[1024];             // B fragments hi: [kk][nh][lane]
__device__ uint2 g_Bfl[1024];             // B fragments lo
__device__ float g_Y[8 * 16 * 128 * 128]; // 8 MB, (b,e,h,w)
__device__ float g_psum[8 * 16 * 128];    // [b][e][hr]
__device__ float g_psq[8 * 16 * 128];
__device__ float g_mean[64];
__device__ float g_istd[64];

// ---------------------------------------------------------------------------
// Kernel 1: fold FFT + complex linear + IFFT.real + conv into B[256][16], g0.
// ---------------------------------------------------------------------------
__global__ void precompute_kernel(const float* __restrict__ wr, const float* __restrict__ wi,
                                  const float* __restrict__ br, const float* __restrict__ bi,
                                  const float* __restrict__ cw, const float* __restrict__ cb) {
    __shared__ float cosT[256], sinT[256];
    __shared__ float swr[16 * 257], swi[16 * 257];
    __shared__ float sCR[256], sCI[256];
    __shared__ float sMR[256], sMI[256];
    const int tid = threadIdx.x;

    {
        double s, c;
        sincos(2.0 * PI_D * (double)tid / 256.0, &s, &c);
        cosT[tid] = (float)c; sinT[tid] = (float)s;
    }
    for (int i = tid; i < 4096; i += 256) {
        int d = i >> 8, k = i & 255;
        swr[d * 257 + k] = wr[i];
        swi[d * 257 + k] = wi[i];
    }
    __syncthreads();

    const int hi4 = tid >> 4, lo4 = tid & 15;
    {   // CR/CI
        float cr = 0.f, ci = 0.f;
#pragma unroll
        for (int m = 0; m < 16; m++) {
            int t = ((hi4 * m) & 15) << 4;
            float w = cw[lo4 * 16 + m];
            cr += w * cosT[t];
            ci += w * sinT[t];
        }
        sCR[hi4 * 16 + lo4] = cr; sCI[hi4 * 16 + lo4] = ci;
    }
    {   // MR/MI
        const int jl = hi4, d = lo4;
        const int j = (blockIdx.x << 4) + jl;
        const float* a  = swr + d * 257;
        const float* bb = swi + d * 257;
        float mr0 = 0.f, mi0 = 0.f, mr1 = 0.f, mi1 = 0.f;
        float mr2 = 0.f, mi2 = 0.f, mr3 = 0.f, mi3 = 0.f;
        for (int k = 0; k < 256; k += 4) {
            int t0 = (k * j) & 255, t1 = (t0 + j) & 255;
            int t2 = (t1 + j) & 255, t3 = (t2 + j) & 255;
            float c0 = cosT[t0], s0 = sinT[t0], a0 = a[k],     b0 = bb[k];
            float c1 = cosT[t1], s1 = sinT[t1], a1 = a[k + 1], b1 = bb[k + 1];
            float c2 = cosT[t2], s2 = sinT[t2], a2 = a[k + 2], b2 = bb[k + 2];
            float c3 = cosT[t3], s3 = sinT[t3], a3 = a[k + 3], b3 = bb[k + 3];
            mr0 += a0 * c0 + b0 * s0;  mi0 += b0 * c0 - a0 * s0;
            mr1 += a1 * c1 + b1 * s1;  mi1 += b1 * c1 - a1 * s1;
            mr2 += a2 * c2 + b2 * s2;  mi2 += b2 * c2 - a2 * s2;
            mr3 += a3 * c3 + b3 * s3;  mi3 += b3 * c3 - a3 * s3;
        }
        sMR[jl * 16 + d] = (mr0 + mr1) + (mr2 + mr3);
        sMI[jl * 16 + d] = (mi0 + mi1) + (mi2 + mi3);
    }
    __syncthreads();
    {   // B[k][e]
        const int jl = hi4, e = lo4;
        const int k = (blockIdx.x << 4) + jl;
        float g = 0.f;
#pragma unroll
        for (int d = 0; d < 16; d++)
            g += sMR[jl * 16 + d] * sCR[d * 16 + e] - sMI[jl * 16 + d] * sCI[d * 16 + e];
        g_B[k * 16 + e] = g * (1.0f / 64.0f);
    }
    if (blockIdx.x == 0 && tid < 16) {
        float acc = cb[tid];
        for (int m = 0; m < 16; m++) {
            float b0 = 0.f;
            for (int d = 0; d < 16; d++) {
                int t = ((d * m) & 15) << 4;
                b0 += br[d] * cosT[t] - bi[d] * sinT[t];
            }
            acc += cw[tid * 16 + m] * b0 * 0.25f;
        }
        g_g0[tid] = acc;
    }
}

// ---------------------------------------------------------------------------
// Kernel 1b: build per-lane B fragments (m16n8k16 col-major B layout).
// Fragment t = kk*64 + nh*32 + lane:
//   b.x = {B[k0][n] lo, B[k0+1][n] hi},  b.y = {B[k0+8][n], B[k0+9][n]}
//   k0 = 16kk + 2(l&3), n = 8nh + (l>>2)
// ---------------------------------------------------------------------------
__global__ void bfrag_kernel() {
    const int t = blockIdx.x * 256 + threadIdx.x;   // 1024 total
    const int l = t & 31, nh = (t >> 5) & 1, kk = t >> 6;
    const int q = l & 3, g = l >> 2;
    const int n = nh * 8 + g;
    const int k0 = kk * 16 + 2 * q;
    float B0 = g_B[(k0)     * 16 + n];
    float B1 = g_B[(k0 + 1) * 16 + n];
    float B2 = g_B[(k0 + 8) * 16 + n];
    float B3 = g_B[(k0 + 9) * 16 + n];
    uint32_t u0 = __float_as_uint(B0), u1 = __float_as_uint(B1);
    uint32_t u2 = __float_as_uint(B2), u3 = __float_as_uint(B3);
    uint2 h, lo;
    h.x = __byte_perm(u0, u1, 0x7632);
    h.y = __byte_perm(u2, u3, 0x7632);
    float l0 = B0 - __uint_as_float(u0 & 0xFFFF0000u);
    float l1 = B1 - __uint_as_float(u1 & 0xFFFF0000u);
    float l2 = B2 - __uint_as_float(u2 & 0xFFFF0000u);
    float l3 = B3 - __uint_as_float(u3 & 0xFFFF0000u);
    asm("cvt.rn.bf16x2.f32 %0, %1, %2;" : "=r"(lo.x) : "f"(l1), "f"(l0));
    asm("cvt.rn.bf16x2.f32 %0, %1, %2;" : "=r"(lo.y) : "f"(l3), "f"(l2));
    g_Bfh[t] = h;
    g_Bfl[t] = lo;
}

// ---------------------------------------------------------------------------
// Main kernel helpers
// ---------------------------------------------------------------------------
__device__ __forceinline__ void split_bf16(float2 f, uint32_t& h, uint32_t& lo) {
    uint32_t u0 = __float_as_uint(f.x), u1 = __float_as_uint(f.y);
    h = __byte_perm(u0, u1, 0x7632);
    float l0 = f.x - __uint_as_float(u0 & 0xFFFF0000u);
    float l1 = f.y - __uint_as_float(u1 & 0xFFFF0000u);
    asm("cvt.rn.bf16x2.f32 %0, %1, %2;" : "=r"(lo) : "f"(l1), "f"(l0));
}
__device__ __forceinline__ void mma16816(float* c, const uint32_t* a, uint2 b) {
    asm("mma.sync.aligned.m16n8k16.row.col.f32.bf16.bf16.f32 "
        "{%0,%1,%2,%3}, {%4,%5,%6,%7}, {%8,%9}, {%0,%1,%2,%3};"
        : "+f"(c[0]), "+f"(c[1]), "+f"(c[2]), "+f"(c[3])
        : "r"(a[0]), "r"(a[1]), "r"(a[2]), "r"(a[3]), "r"(b.x), "r"(b.y));
}

// ---------------------------------------------------------------------------
// Kernel 2 (hot): 1024 blocks x 256 threads (8 warps). Block = one patch row
// (128 patches); warp = 16 patches. A loaded straight from gmem into
// m16n8k16 fragment layout (4 x LDG.64 per k-step, sector-complementary ->
// fully coalesced). 6 HMMA per k-step. Epilogue staged via smem.
// ---------------------------------------------------------------------------
#define SYP 132

__global__ void __launch_bounds__(256) main_kernel(const float* __restrict__ x) {
    __shared__ uint2 sBh[1024];
    __shared__ uint2 sBl[1024];
    __shared__ float sY[16 * SYP];
    const int tid = threadIdx.x;
    const int w = tid >> 5, lane = tid & 31;
    const int b  = blockIdx.x >> 7;
    const int hr = blockIdx.x & 127;

#pragma unroll
    for (int u = 0; u < 4; u++) {
        sBh[tid + (u << 8)] = g_Bfh[tid + (u << 8)];
        sBl[tid + (u << 8)] = g_Bfl[tid + (u << 8)];
    }
    __syncthreads();

    const int g = lane >> 2, q = lane & 3;
    // A pointers (floats): patch pA = w*16 + g, element offset q*2 within row
    const float* aptr = x + (((size_t)b) << 22) + (((size_t)hr) << 15)
                          + (w * 16 + g) * 16 + q * 2;

    float acc0[4] = {0.f, 0.f, 0.f, 0.f};
    float acc1[4] = {0.f, 0.f, 0.f, 0.f};

    float2 f0, f1, f2, f3;
    f0 = *(const float2*)(aptr);
    f1 = *(const float2*)(aptr + 8);
    f2 = *(const float2*)(aptr + 128);
    f3 = *(const float2*)(aptr + 136);

#pragma unroll
    for (int kk = 0; kk < 16; kk++) {
        uint32_t ah[4], al[4];
        split_bf16(f0, ah[0], al[0]);   // row g,   k-low
        split_bf16(f2, ah[1], al[1]);   // row g+8, k-low
        split_bf16(f1, ah[2], al[2]);   // row g,   k-high
        split_bf16(f3, ah[3], al[3]);   // row g+8, k-high

        if (kk < 15) {
            const float* np = aptr + ((kk + 1) << 11);
            f0 = *(const float2*)(np);
            f1 = *(const float2*)(np + 8);
            f2 = *(const float2*)(np + 128);
            f3 = *(const float2*)(np + 136);
        }

        uint2 bh0 = sBh[(kk << 6) + lane];
        uint2 bh1 = sBh[(kk << 6) + 32 + lane];
        uint2 bl0 = sBl[(kk << 6) + lane];
        uint2 bl1 = sBl[(kk << 6) + 32 + lane];

        mma16816(acc0, ah, bh0);
        mma16816(acc1, ah, bh1);
        mma16816(acc0, al, bh0);
        mma16816(acc1, al, bh1);
        mma16816(acc0, ah, bl0);
        mma16816(acc1, ah, bl1);
    }

    // scatter C fragments to sY[e][p]
    {
        const int p_lo = w * 16 + g, p_hi = p_lo + 8;
        sY[(2 * q + 0) * SYP + p_lo] = acc0[0];
        sY[(2 * q + 1) * SYP + p_lo] = acc0[1];
        sY[(2 * q + 0) * SYP + p_hi] = acc0[2];
        sY[(2 * q + 1) * SYP + p_hi] = acc0[3];
        sY[(8 + 2 * q) * SYP + p_lo] = acc1[0];
        sY[(9 + 2 * q) * SYP + p_lo] = acc1[1];
        sY[(8 + 2 * q) * SYP + p_hi] = acc1[2];
        sY[(9 + 2 * q) * SYP + p_hi] = acc1[3];
    }
    __syncthreads();

    // staging pass: thread t -> channel e = t>>4, 8 consecutive patches.
    {
        const int e = tid >> 4, i2 = tid & 15;
        const float g0v = g_g0[e];
        float v[8];
        float4 va = *(const float4*)&sY[e * SYP + i2 * 8];
        float4 vb = *(const float4*)&sY[e * SYP + i2 * 8 + 4];
        v[0] = va.x + g0v; v[1] = va.y + g0v; v[2] = va.z + g0v; v[3] = va.w + g0v;
        v[4] = vb.x + g0v; v[5] = vb.y + g0v; v[6] = vb.z + g0v; v[7] = vb.w + g0v;

        float s = 0.f, qq = 0.f;
#pragma unroll
        for (int j = 0; j < 8; j++) { s += v[j]; qq += v[j] * v[j]; }

        float4 oa = make_float4(v[0], v[1], v[2], v[3]);
        float4 ob = make_float4(v[4], v[5], v[6], v[7]);
        float* dst = &g_Y[(((size_t)(b * 16 + e)) << 14) + (hr << 7) + i2 * 8];
        *(float4*)dst = oa;
        *(float4*)(dst + 4) = ob;

#pragma unroll
        for (int off = 8; off; off >>= 1) {
            s  += __shfl_down_sync(0xffffffffu, s, off, 16);
            qq += __shfl_down_sync(0xffffffffu, qq, off, 16);
        }
        if (i2 == 0) {
            g_psum[(b * 16 + e) * 128 + hr] = s;
            g_psq[(b * 16 + e) * 128 + hr] = qq;
        }
    }
}

// ---------------------------------------------------------------------------
// Kernel 3: per (batch,group) stats from per-channel partials.
// N = 2 channels * 128 * 128 = 32768.
// ---------------------------------------------------------------------------
__global__ void stats_kernel() {
    const int tid = threadIdx.x;          // 512
    const int bg = tid >> 3, k = tid & 7;
    const int b = bg >> 3, grp = bg & 7;
    float s = 0.f, q = 0.f;
#pragma unroll
    for (int ee = 0; ee < 2; ee++) {
        const int base = (b * 16 + grp * 2 + ee) * 128;
#pragma unroll
        for (int i = 0; i < 16; i++) {
            s += g_psum[base + k + (i << 3)];
            q += g_psq[base + k + (i << 3)];
        }
    }
#pragma unroll
    for (int off = 4; off; off >>= 1) {
        s += __shfl_down_sync(0xffffffffu, s, off, 8);
        q += __shfl_down_sync(0xffffffffu, q, off, 8);
    }
    if (k == 0) {
        const float invN = 1.0f / 32768.0f;
        float mean = s * invN;
        float var  = q * invN - mean * mean;
        g_mean[bg] = mean;
        g_istd[bg] = rsqrtf(var + 1e-5f);
    }
}

// ---------------------------------------------------------------------------
// Kernel 4: normalize + affine. 524288 threads, one float4 each.
// ---------------------------------------------------------------------------
__global__ void __launch_bounds__(512) finalize_kernel(const float* __restrict__ gamma,
                                                       const float* __restrict__ beta,
                                                       float* __restrict__ out) {
    const int idx = blockIdx.x * 512 + threadIdx.x;       // 524288 float4
    float4 v = ((const float4*)g_Y)[idx];
    const int plane = idx >> 12;
    const int e = plane & 15, b = plane >> 4;
    const int bg = b * 8 + (e >> 1);
    const float is = g_istd[bg];
    const float sc = is * gamma[e];
    const float sh = beta[e] - g_mean[bg] * sc;
    v.x = v.x * sc + sh; v.y = v.y * sc + sh;
    v.z = v.z * sc + sh; v.w = v.w * sc + sh;
    ((float4*)out)[idx] = v;
}

extern "C" void kernel_launch(void* const* d_in, const int* in_sizes, int n_in,
                              void* d_out, int out_size) {
    const float* x     = (const float*)d_in[0];
    const float* wr    = (const float*)d_in[1];
    const float* wi    = (const float*)d_in[2];
    const float* br    = (const float*)d_in[3];
    const float* bi    = (const float*)d_in[4];
    const float* cw    = (const float*)d_in[5];
    const float* cb    = (const float*)d_in[6];
    const float* gamma = (const float*)d_in[7];
    const float* beta  = (const float*)d_in[8];
    float* out = (float*)d_out;

    precompute_kernel<<<16, 256>>>(wr, wi, br, bi, cw, cb);
    bfrag_kernel<<<4, 256>>>();
    main_kernel<<<1024, 256>>>(x);
    stats_kernel<<<1, 512>>>();
    finalize_kernel<<<1024, 512>>>(gamma, beta, out);
}

// round 11
// speedup vs baseline: 1.6766x; 1.0963x over previous
#include <cuda_runtime.h>
#include <cuda_bf16.h>
#include <math.h>
#include <stdint.h>

// ---------------------------------------------------------------------------
// CFNO folded: patchify(16x16) -> FFT(256) -> complex linear -> IFFT(16).real
// -> 1x1 conv == y = p @ G + g0 (real G[256][16]); then GroupNorm(8,16).
//
// Main kernel: HMMA (mma.sync.m16n8k16 bf16) with exact hi/lo split:
//   x = hi + lo (hi = fp32 top-16 bits, exact bf16; lo = x - hi)
//   y = Ah*Bh + Al*Bh + Ah*Bl   (AlBl ~2^-16 dropped)
// A loaded gmem -> registers directly in fragment layout (no smem staging).
// ---------------------------------------------------------------------------

#define PI_D 3.141592653589793238462643383279502884

__device__ float g_g0[16];
__device__ uint2 g_Bfh[1024];             // B fragments hi: [kk][nh][lane]
__device__ uint2 g_Bfl[1024];             // B fragments lo
__device__ float g_Y[8 * 16 * 128 * 128]; // 8 MB, (b,e,h,w)
__device__ float g_psum[8 * 16 * 128];    // [b][e][hr]
__device__ float g_psq[8 * 16 * 128];
__device__ float g_mean[64];
__device__ float g_istd[64];

// ---------------------------------------------------------------------------
// Kernel 1: fold chain into B[256][16] and emit m16n8k16 B fragments.
// Block bid owns B rows [16*bid, 16*bid+16) == fragment group kk = bid.
// ---------------------------------------------------------------------------
__global__ void precompute_kernel(const float* __restrict__ wr, const float* __restrict__ wi,
                                  const float* __restrict__ br, const float* __restrict__ bi,
                                  const float* __restrict__ cw, const float* __restrict__ cb) {
    __shared__ float cosT[256], sinT[256];
    __shared__ float swr[16 * 257], swi[16 * 257];
    __shared__ float sCR[256], sCI[256];
    __shared__ float sMR[256], sMI[256];
    __shared__ float sB[256];              // this block's B rows [jl][e]
    const int tid = threadIdx.x;

    {
        double s, c;
        sincos(2.0 * PI_D * (double)tid / 256.0, &s, &c);
        cosT[tid] = (float)c; sinT[tid] = (float)s;
    }
    for (int i = tid; i < 4096; i += 256) {
        int d = i >> 8, k = i & 255;
        swr[d * 257 + k] = wr[i];
        swi[d * 257 + k] = wi[i];
    }
    __syncthreads();

    const int hi4 = tid >> 4, lo4 = tid & 15;
    {   // CR/CI
        float cr = 0.f, ci = 0.f;
#pragma unroll
        for (int m = 0; m < 16; m++) {
            int t = ((hi4 * m) & 15) << 4;
            float w = cw[lo4 * 16 + m];
            cr += w * cosT[t];
            ci += w * sinT[t];
        }
        sCR[hi4 * 16 + lo4] = cr; sCI[hi4 * 16 + lo4] = ci;
    }
    {   // MR/MI
        const int jl = hi4, d = lo4;
        const int j = (blockIdx.x << 4) + jl;
        const float* a  = swr + d * 257;
        const float* bb = swi + d * 257;
        float mr0 = 0.f, mi0 = 0.f, mr1 = 0.f, mi1 = 0.f;
        float mr2 = 0.f, mi2 = 0.f, mr3 = 0.f, mi3 = 0.f;
        for (int k = 0; k < 256; k += 4) {
            int t0 = (k * j) & 255, t1 = (t0 + j) & 255;
            int t2 = (t1 + j) & 255, t3 = (t2 + j) & 255;
            float c0 = cosT[t0], s0 = sinT[t0], a0 = a[k],     b0 = bb[k];
            float c1 = cosT[t1], s1 = sinT[t1], a1 = a[k + 1], b1 = bb[k + 1];
            float c2 = cosT[t2], s2 = sinT[t2], a2 = a[k + 2], b2 = bb[k + 2];
            float c3 = cosT[t3], s3 = sinT[t3], a3 = a[k + 3], b3 = bb[k + 3];
            mr0 += a0 * c0 + b0 * s0;  mi0 += b0 * c0 - a0 * s0;
            mr1 += a1 * c1 + b1 * s1;  mi1 += b1 * c1 - a1 * s1;
            mr2 += a2 * c2 + b2 * s2;  mi2 += b2 * c2 - a2 * s2;
            mr3 += a3 * c3 + b3 * s3;  mi3 += b3 * c3 - a3 * s3;
        }
        sMR[jl * 16 + d] = (mr0 + mr1) + (mr2 + mr3);
        sMI[jl * 16 + d] = (mi0 + mi1) + (mi2 + mi3);
    }
    __syncthreads();
    {   // B row jl, col e (local)
        const int jl = hi4, e = lo4;
        float g = 0.f;
#pragma unroll
        for (int d = 0; d < 16; d++)
            g += sMR[jl * 16 + d] * sCR[d * 16 + e] - sMI[jl * 16 + d] * sCI[d * 16 + e];
        sB[jl * 16 + e] = g * (1.0f / 64.0f);
    }
    __syncthreads();
    if (tid < 64) {   // emit fragments for kk = blockIdx.x
        const int lane = tid & 31, nh = tid >> 5;
        const int q = lane & 3, gg = lane >> 2;
        const int n = nh * 8 + gg;
        const int j0 = 2 * q;
        float B0 = sB[(j0)     * 16 + n];
        float B1 = sB[(j0 + 1) * 16 + n];
        float B2 = sB[(j0 + 8) * 16 + n];
        float B3 = sB[(j0 + 9) * 16 + n];
        uint32_t u0 = __float_as_uint(B0), u1 = __float_as_uint(B1);
        uint32_t u2 = __float_as_uint(B2), u3 = __float_as_uint(B3);
        uint2 h, lo;
        h.x = __byte_perm(u0, u1, 0x7632);
        h.y = __byte_perm(u2, u3, 0x7632);
        float l0 = B0 - __uint_as_float(u0 & 0xFFFF0000u);
        float l1 = B1 - __uint_as_float(u1 & 0xFFFF0000u);
        float l2 = B2 - __uint_as_float(u2 & 0xFFFF0000u);
        float l3 = B3 - __uint_as_float(u3 & 0xFFFF0000u);
        asm("cvt.rn.bf16x2.f32 %0, %1, %2;" : "=r"(lo.x) : "f"(l1), "f"(l0));
        asm("cvt.rn.bf16x2.f32 %0, %1, %2;" : "=r"(lo.y) : "f"(l3), "f"(l2));
        const int t = (blockIdx.x << 6) + (nh << 5) + lane;
        g_Bfh[t] = h;
        g_Bfl[t] = lo;
    }
    if (blockIdx.x == 0 && tid < 16) {
        float acc = cb[tid];
        for (int m = 0; m < 16; m++) {
            float b0 = 0.f;
            for (int d = 0; d < 16; d++) {
                int t = ((d * m) & 15) << 4;
                b0 += br[d] * cosT[t] - bi[d] * sinT[t];
            }
            acc += cw[tid * 16 + m] * b0 * 0.25f;
        }
        g_g0[tid] = acc;
    }
}

// ---------------------------------------------------------------------------
// Main kernel helpers
// ---------------------------------------------------------------------------
__device__ __forceinline__ void split_bf16(float2 f, uint32_t& h, uint32_t& lo) {
    uint32_t u0 = __float_as_uint(f.x), u1 = __float_as_uint(f.y);
    h = __byte_perm(u0, u1, 0x7632);
    float l0 = f.x - __uint_as_float(u0 & 0xFFFF0000u);
    float l1 = f.y - __uint_as_float(u1 & 0xFFFF0000u);
    asm("cvt.rn.bf16x2.f32 %0, %1, %2;" : "=r"(lo) : "f"(l1), "f"(l0));
}
__device__ __forceinline__ void mma16816(float* c, const uint32_t* a, uint2 b) {
    asm("mma.sync.aligned.m16n8k16.row.col.f32.bf16.bf16.f32 "
        "{%0,%1,%2,%3}, {%4,%5,%6,%7}, {%8,%9}, {%0,%1,%2,%3};"
        : "+f"(c[0]), "+f"(c[1]), "+f"(c[2]), "+f"(c[3])
        : "r"(a[0]), "r"(a[1]), "r"(a[2]), "r"(a[3]), "r"(b.x), "r"(b.y));
}

// ---------------------------------------------------------------------------
// Kernel 2 (hot): 1024 blocks x 256 threads (8 warps). Block = one patch row
// (128 patches); warp = 16 patches. A loaded straight from gmem into
// m16n8k16 fragment layout (4 x LDG.64 per k-step, sector-minimal).
// 6 HMMA per k-step. Epilogue staged via smem.
// ---------------------------------------------------------------------------
#define SYP 132

__global__ void __launch_bounds__(256) main_kernel(const float* __restrict__ x) {
    __shared__ uint2 sBh[1024];
    __shared__ uint2 sBl[1024];
    __shared__ float sY[16 * SYP];
    const int tid = threadIdx.x;
    const int w = tid >> 5, lane = tid & 31;
    const int b  = blockIdx.x >> 7;
    const int hr = blockIdx.x & 127;

#pragma unroll
    for (int u = 0; u < 4; u++) {
        sBh[tid + (u << 8)] = g_Bfh[tid + (u << 8)];
        sBl[tid + (u << 8)] = g_Bfl[tid + (u << 8)];
    }
    __syncthreads();

    const int g = lane >> 2, q = lane & 3;
    const float* aptr = x + (((size_t)b) << 22) + (((size_t)hr) << 15)
                          + (w * 16 + g) * 16 + q * 2;

    float acc0[4] = {0.f, 0.f, 0.f, 0.f};
    float acc1[4] = {0.f, 0.f, 0.f, 0.f};

    float2 f0, f1, f2, f3;
    f0 = *(const float2*)(aptr);
    f1 = *(const float2*)(aptr + 8);
    f2 = *(const float2*)(aptr + 128);
    f3 = *(const float2*)(aptr + 136);

#pragma unroll
    for (int kk = 0; kk < 16; kk++) {
        uint32_t ah[4], al[4];
        split_bf16(f0, ah[0], al[0]);   // row g,   k-low
        split_bf16(f2, ah[1], al[1]);   // row g+8, k-low
        split_bf16(f1, ah[2], al[2]);   // row g,   k-high
        split_bf16(f3, ah[3], al[3]);   // row g+8, k-high

        if (kk < 15) {
            const float* np = aptr + ((kk + 1) << 11);
            f0 = *(const float2*)(np);
            f1 = *(const float2*)(np + 8);
            f2 = *(const float2*)(np + 128);
            f3 = *(const float2*)(np + 136);
        }

        uint2 bh0 = sBh[(kk << 6) + lane];
        uint2 bh1 = sBh[(kk << 6) + 32 + lane];
        uint2 bl0 = sBl[(kk << 6) + lane];
        uint2 bl1 = sBl[(kk << 6) + 32 + lane];

        mma16816(acc0, ah, bh0);
        mma16816(acc1, ah, bh1);
        mma16816(acc0, al, bh0);
        mma16816(acc1, al, bh1);
        mma16816(acc0, ah, bl0);
        mma16816(acc1, ah, bl1);
    }

    // scatter C fragments to sY[e][p]
    {
        const int p_lo = w * 16 + g, p_hi = p_lo + 8;
        sY[(2 * q + 0) * SYP + p_lo] = acc0[0];
        sY[(2 * q + 1) * SYP + p_lo] = acc0[1];
        sY[(2 * q + 0) * SYP + p_hi] = acc0[2];
        sY[(2 * q + 1) * SYP + p_hi] = acc0[3];
        sY[(8 + 2 * q) * SYP + p_lo] = acc1[0];
        sY[(9 + 2 * q) * SYP + p_lo] = acc1[1];
        sY[(8 + 2 * q) * SYP + p_hi] = acc1[2];
        sY[(9 + 2 * q) * SYP + p_hi] = acc1[3];
    }
    __syncthreads();

    // staging pass: thread t -> channel e = t>>4, 8 consecutive patches.
    {
        const int e = tid >> 4, i2 = tid & 15;
        const float g0v = g_g0[e];
        float v[8];
        float4 va = *(const float4*)&sY[e * SYP + i2 * 8];
        float4 vb = *(const float4*)&sY[e * SYP + i2 * 8 + 4];
        v[0] = va.x + g0v; v[1] = va.y + g0v; v[2] = va.z + g0v; v[3] = va.w + g0v;
        v[4] = vb.x + g0v; v[5] = vb.y + g0v; v[6] = vb.z + g0v; v[7] = vb.w + g0v;

        float s = 0.f, qq = 0.f;
#pragma unroll
        for (int j = 0; j < 8; j++) { s += v[j]; qq += v[j] * v[j]; }

        float4 oa = make_float4(v[0], v[1], v[2], v[3]);
        float4 ob = make_float4(v[4], v[5], v[6], v[7]);
        float* dst = &g_Y[(((size_t)(b * 16 + e)) << 14) + (hr << 7) + i2 * 8];
        *(float4*)dst = oa;
        *(float4*)(dst + 4) = ob;

#pragma unroll
        for (int off = 8; off; off >>= 1) {
            s  += __shfl_down_sync(0xffffffffu, s, off, 16);
            qq += __shfl_down_sync(0xffffffffu, qq, off, 16);
        }
        if (i2 == 0) {
            g_psum[(b * 16 + e) * 128 + hr] = s;
            g_psq[(b * 16 + e) * 128 + hr] = qq;
        }
    }
}

// ---------------------------------------------------------------------------
// Kernel 3: stats, fully parallel: 64 blocks (one per batch-group) x 128 thr.
// Each thread loads 2 channels' partials for one hr; tree reduce.
// ---------------------------------------------------------------------------
__global__ void __launch_bounds__(128) stats_kernel() {
    __shared__ float ss[4], sq[4];
    const int bg = blockIdx.x;
    const int b = bg >> 3, grp = bg & 7;
    const int tid = threadIdx.x;
    const int base0 = (b * 16 + grp * 2) * 128;
    const int base1 = base0 + 128;
    float s = g_psum[base0 + tid] + g_psum[base1 + tid];
    float q = g_psq[base0 + tid]  + g_psq[base1 + tid];
#pragma unroll
    for (int off = 16; off; off >>= 1) {
        s += __shfl_down_sync(0xffffffffu, s, off);
        q += __shfl_down_sync(0xffffffffu, q, off);
    }
    const int lane = tid & 31, wrp = tid >> 5;
    if (lane == 0) { ss[wrp] = s; sq[wrp] = q; }
    __syncthreads();
    if (tid == 0) {
        float st = ss[0] + ss[1] + ss[2] + ss[3];
        float qt = sq[0] + sq[1] + sq[2] + sq[3];
        const float invN = 1.0f / 32768.0f;
        float mean = st * invN;
        float var  = qt * invN - mean * mean;
        g_mean[bg] = mean;
        g_istd[bg] = rsqrtf(var + 1e-5f);
    }
}

// ---------------------------------------------------------------------------
// Kernel 4: normalize + affine. 4 independent float4 per thread (MLP=4).
// ---------------------------------------------------------------------------
__global__ void __launch_bounds__(256) finalize_kernel(const float* __restrict__ gamma,
                                                       const float* __restrict__ beta,
                                                       float* __restrict__ out) {
    const int t = blockIdx.x * 256 + threadIdx.x;       // 131072 threads
    float4 v[4];
#pragma unroll
    for (int r = 0; r < 4; r++) v[r] = ((const float4*)g_Y)[t + (r << 17)];
#pragma unroll
    for (int r = 0; r < 4; r++) {
        const int idx = t + (r << 17);
        const int plane = idx >> 12;
        const int e = plane & 15, b = plane >> 4;
        const int bg = b * 8 + (e >> 1);
        const float is = g_istd[bg];
        const float sc = is * gamma[e];
        const float sh = beta[e] - g_mean[bg] * sc;
        float4 o;
        o.x = v[r].x * sc + sh; o.y = v[r].y * sc + sh;
        o.z = v[r].z * sc + sh; o.w = v[r].w * sc + sh;
        ((float4*)out)[idx] = o;
    }
}

extern "C" void kernel_launch(void* const* d_in, const int* in_sizes, int n_in,
                              void* d_out, int out_size) {
    const float* x     = (const float*)d_in[0];
    const float* wr    = (const float*)d_in[1];
    const float* wi    = (const float*)d_in[2];
    const float* br    = (const float*)d_in[3];
    const float* bi    = (const float*)d_in[4];
    const float* cw    = (const float*)d_in[5];
    const float* cb    = (const float*)d_in[6];
    const float* gamma = (const float*)d_in[7];
    const float* beta  = (const float*)d_in[8];
    float* out = (float*)d_out;

    precompute_kernel<<<16, 256>>>(wr, wi, br, bi, cw, cb);
    main_kernel<<<1024, 256>>>(x);
    stats_kernel<<<64, 128>>>();
    finalize_kernel<<<512, 256>>>(gamma, beta, out);
}

// round 12
// speedup vs baseline: 1.7066x; 1.0179x over previous
#include <cuda_runtime.h>
#include <cuda_bf16.h>
#include <math.h>
#include <stdint.h>

// ---------------------------------------------------------------------------
// CFNO folded: patchify(16x16) -> FFT(256) -> complex linear -> IFFT(16).real
// -> 1x1 conv == y = p @ G + g0 (real G[256][16]); then GroupNorm(8,16).
//
// Main kernel: HMMA (mma.sync.m16n8k16 bf16) with exact hi/lo split:
//   x = hi + lo (hi = fp32 top-16 bits, exact bf16; lo = x - hi)
//   y = Ah*Bh + Al*Bh + Ah*Bl   (AlBl ~2^-16 dropped)
// A gmem -> registers in fragment layout; prefetch distance 2.
// ---------------------------------------------------------------------------

#define PI_D 3.141592653589793238462643383279502884

__device__ float g_g0[16];
__device__ uint2 g_Bfh[1024];             // B fragments hi: [kk][lane][nh]
__device__ uint2 g_Bfl[1024];             // B fragments lo
__device__ float g_Y[8 * 16 * 128 * 128]; // 8 MB, (b,e,h,w)
__device__ float g_psum[8 * 16 * 128];    // [b][e][hr]
__device__ float g_psq[8 * 16 * 128];
__device__ float g_sc[128];               // per (b*16+e) scale
__device__ float g_sh[128];               // per (b*16+e) shift

// ---------------------------------------------------------------------------
// Kernel 1: fold chain into B[256][16] and emit m16n8k16 B fragments.
// 1024 threads: DFT k-loop split 4 ways (ks = tid&3), shfl-quad reduce.
// Block bid owns B rows [16*bid, +16) == fragment group kk = bid.
// ---------------------------------------------------------------------------
__global__ void __launch_bounds__(1024) precompute_kernel(
        const float* __restrict__ wr, const float* __restrict__ wi,
        const float* __restrict__ br, const float* __restrict__ bi,
        const float* __restrict__ cw, const float* __restrict__ cb) {
    __shared__ float cosT[256], sinT[256];
    __shared__ float swr[16 * 257], swi[16 * 257];
    __shared__ float sCR[256], sCI[256];
    __shared__ float sMR[256], sMI[256];
    __shared__ float sB[256];
    const int tid = threadIdx.x;

    if (tid < 256) {
        double s, c;
        sincos(2.0 * PI_D * (double)tid / 256.0, &s, &c);
        cosT[tid] = (float)c; sinT[tid] = (float)s;
    }
    for (int i = tid; i < 4096; i += 1024) {
        int d = i >> 8, k = i & 255;
        swr[d * 257 + k] = wr[i];
        swi[d * 257 + k] = wi[i];
    }
    __syncthreads();

    if (tid < 256) {   // CR/CI: d = tid>>4, e = tid&15
        const int dd = tid >> 4, e = tid & 15;
        float cr = 0.f, ci = 0.f;
#pragma unroll
        for (int m = 0; m < 16; m++) {
            int t = ((dd * m) & 15) << 4;
            float w = cw[e * 16 + m];
            cr += w * cosT[t];
            ci += w * sinT[t];
        }
        sCR[dd * 16 + e] = cr; sCI[dd * 16 + e] = ci;
    }
    {   // MR/MI: jl = tid>>6, d = (tid>>2)&15, k-slice ks = tid&3
        const int jl = tid >> 6, d = (tid >> 2) & 15, ks = tid & 3;
        const int j = (blockIdx.x << 4) + jl;
        const float* a  = swr + d * 257;
        const float* bb = swi + d * 257;
        const int k0 = ks << 6;
        float mr0 = 0.f, mi0 = 0.f, mr1 = 0.f, mi1 = 0.f;
        float mr2 = 0.f, mi2 = 0.f, mr3 = 0.f, mi3 = 0.f;
        for (int k = k0; k < k0 + 64; k += 4) {
            int t0 = (k * j) & 255, t1 = (t0 + j) & 255;
            int t2 = (t1 + j) & 255, t3 = (t2 + j) & 255;
            float c0 = cosT[t0], s0 = sinT[t0], a0 = a[k],     b0 = bb[k];
            float c1 = cosT[t1], s1 = sinT[t1], a1 = a[k + 1], b1 = bb[k + 1];
            float c2 = cosT[t2], s2 = sinT[t2], a2 = a[k + 2], b2 = bb[k + 2];
            float c3 = cosT[t3], s3 = sinT[t3], a3 = a[k + 3], b3 = bb[k + 3];
            mr0 += a0 * c0 + b0 * s0;  mi0 += b0 * c0 - a0 * s0;
            mr1 += a1 * c1 + b1 * s1;  mi1 += b1 * c1 - a1 * s1;
            mr2 += a2 * c2 + b2 * s2;  mi2 += b2 * c2 - a2 * s2;
            mr3 += a3 * c3 + b3 * s3;  mi3 += b3 * c3 - a3 * s3;
        }
        float mr = (mr0 + mr1) + (mr2 + mr3);
        float mi = (mi0 + mi1) + (mi2 + mi3);
        mr += __shfl_xor_sync(0xffffffffu, mr, 1);
        mi += __shfl_xor_sync(0xffffffffu, mi, 1);
        mr += __shfl_xor_sync(0xffffffffu, mr, 2);
        mi += __shfl_xor_sync(0xffffffffu, mi, 2);
        if (ks == 0) { sMR[jl * 16 + d] = mr; sMI[jl * 16 + d] = mi; }
    }
    __syncthreads();
    if (tid < 256) {   // B row jl, col e
        const int jl = tid >> 4, e = tid & 15;
        float g = 0.f;
#pragma unroll
        for (int d = 0; d < 16; d++)
            g += sMR[jl * 16 + d] * sCR[d * 16 + e] - sMI[jl * 16 + d] * sCI[d * 16 + e];
        sB[jl * 16 + e] = g * (1.0f / 64.0f);
    }
    __syncthreads();
    if (tid < 64) {   // emit fragments for kk = blockIdx.x; layout [kk][lane][nh]
        const int lane = tid & 31, nh = tid >> 5;
        const int q = lane & 3, gg = lane >> 2;
        const int n = nh * 8 + gg;
        const int j0 = 2 * q;
        float B0 = sB[(j0)     * 16 + n];
        float B1 = sB[(j0 + 1) * 16 + n];
        float B2 = sB[(j0 + 8) * 16 + n];
        float B3 = sB[(j0 + 9) * 16 + n];
        uint32_t u0 = __float_as_uint(B0), u1 = __float_as_uint(B1);
        uint32_t u2 = __float_as_uint(B2), u3 = __float_as_uint(B3);
        uint2 h, lo;
        h.x = __byte_perm(u0, u1, 0x7632);
        h.y = __byte_perm(u2, u3, 0x7632);
        float l0 = B0 - __uint_as_float(u0 & 0xFFFF0000u);
        float l1 = B1 - __uint_as_float(u1 & 0xFFFF0000u);
        float l2 = B2 - __uint_as_float(u2 & 0xFFFF0000u);
        float l3 = B3 - __uint_as_float(u3 & 0xFFFF0000u);
        asm("cvt.rn.bf16x2.f32 %0, %1, %2;" : "=r"(lo.x) : "f"(l1), "f"(l0));
        asm("cvt.rn.bf16x2.f32 %0, %1, %2;" : "=r"(lo.y) : "f"(l3), "f"(l2));
        const int t = (blockIdx.x << 6) + lane * 2 + nh;
        g_Bfh[t] = h;
        g_Bfl[t] = lo;
    }
    if (blockIdx.x == 0 && tid < 16) {
        float acc = cb[tid];
        for (int m = 0; m < 16; m++) {
            float b0 = 0.f;
            for (int d = 0; d < 16; d++) {
                int t = ((d * m) & 15) << 4;
                b0 += br[d] * cosT[t] - bi[d] * sinT[t];
            }
            acc += cw[tid * 16 + m] * b0 * 0.25f;
        }
        g_g0[tid] = acc;
    }
}

// ---------------------------------------------------------------------------
// Main kernel helpers
// ---------------------------------------------------------------------------
__device__ __forceinline__ void split_bf16(float2 f, uint32_t& h, uint32_t& lo) {
    uint32_t u0 = __float_as_uint(f.x), u1 = __float_as_uint(f.y);
    h = __byte_perm(u0, u1, 0x7632);
    float l0 = f.x - __uint_as_float(u0 & 0xFFFF0000u);
    float l1 = f.y - __uint_as_float(u1 & 0xFFFF0000u);
    asm("cvt.rn.bf16x2.f32 %0, %1, %2;" : "=r"(lo) : "f"(l1), "f"(l0));
}
__device__ __forceinline__ void mma16816(float* c, const uint32_t* a, uint2 b) {
    asm("mma.sync.aligned.m16n8k16.row.col.f32.bf16.bf16.f32 "
        "{%0,%1,%2,%3}, {%4,%5,%6,%7}, {%8,%9}, {%0,%1,%2,%3};"
        : "+f"(c[0]), "+f"(c[1]), "+f"(c[2]), "+f"(c[3])
        : "r"(a[0]), "r"(a[1]), "r"(a[2]), "r"(a[3]), "r"(b.x), "r"(b.y));
}

// ---------------------------------------------------------------------------
// Kernel 2 (hot): 1024 blocks x 256 threads (8 warps). Block = one patch row;
// warp = 16 patches. A loaded straight from gmem into fragment layout with
// PREFETCH DISTANCE 2 (8 LDG.64 in flight). B via 2x LDS.128 per k-step.
// ---------------------------------------------------------------------------
#define SYP 132

__global__ void __launch_bounds__(256) main_kernel(const float* __restrict__ x) {
    __shared__ uint2 sBh[1024];
    __shared__ uint2 sBl[1024];
    __shared__ float sY[16 * SYP];
    const int tid = threadIdx.x;
    const int w = tid >> 5, lane = tid & 31;
    const int b  = blockIdx.x >> 7;
    const int hr = blockIdx.x & 127;

#pragma unroll
    for (int u = 0; u < 4; u++) {
        sBh[tid + (u << 8)] = g_Bfh[tid + (u << 8)];
        sBl[tid + (u << 8)] = g_Bfl[tid + (u << 8)];
    }
    __syncthreads();

    const int g = lane >> 2, q = lane & 3;
    const float* aptr = x + (((size_t)b) << 22) + (((size_t)hr) << 15)
                          + (w * 16 + g) * 16 + q * 2;

    float acc0[4] = {0.f, 0.f, 0.f, 0.f};
    float acc1[4] = {0.f, 0.f, 0.f, 0.f};

    float2 f[2][4];
#pragma unroll
    for (int p = 0; p < 2; p++) {
        const float* rp = aptr + (p << 11);
        f[p][0] = *(const float2*)(rp);
        f[p][1] = *(const float2*)(rp + 8);
        f[p][2] = *(const float2*)(rp + 128);
        f[p][3] = *(const float2*)(rp + 136);
    }

#pragma unroll
    for (int kk = 0; kk < 16; kk++) {
        const int cur = kk & 1;
        uint32_t ah[4], al[4];
        split_bf16(f[cur][0], ah[0], al[0]);   // row g,   k-low
        split_bf16(f[cur][2], ah[1], al[1]);   // row g+8, k-low
        split_bf16(f[cur][1], ah[2], al[2]);   // row g,   k-high
        split_bf16(f[cur][3], ah[3], al[3]);   // row g+8, k-high

        if (kk < 14) {
            const float* np = aptr + ((kk + 2) << 11);
            f[cur][0] = *(const float2*)(np);
            f[cur][1] = *(const float2*)(np + 8);
            f[cur][2] = *(const float2*)(np + 128);
            f[cur][3] = *(const float2*)(np + 136);
        }

        uint4 vh = ((const uint4*)sBh)[(kk << 5) + lane];
        uint4 vl = ((const uint4*)sBl)[(kk << 5) + lane];
        uint2 bh0 = make_uint2(vh.x, vh.y), bh1 = make_uint2(vh.z, vh.w);
        uint2 bl0 = make_uint2(vl.x, vl.y), bl1 = make_uint2(vl.z, vl.w);

        mma16816(acc0, ah, bh0);
        mma16816(acc1, ah, bh1);
        mma16816(acc0, al, bh0);
        mma16816(acc1, al, bh1);
        mma16816(acc0, ah, bl0);
        mma16816(acc1, ah, bl1);
    }

    // scatter C fragments to sY[e][p]
    {
        const int p_lo = w * 16 + g, p_hi = p_lo + 8;
        sY[(2 * q + 0) * SYP + p_lo] = acc0[0];
        sY[(2 * q + 1) * SYP + p_lo] = acc0[1];
        sY[(2 * q + 0) * SYP + p_hi] = acc0[2];
        sY[(2 * q + 1) * SYP + p_hi] = acc0[3];
        sY[(8 + 2 * q) * SYP + p_lo] = acc1[0];
        sY[(9 + 2 * q) * SYP + p_lo] = acc1[1];
        sY[(8 + 2 * q) * SYP + p_hi] = acc1[2];
        sY[(9 + 2 * q) * SYP + p_hi] = acc1[3];
    }
    __syncthreads();

    // staging: thread -> channel e = tid>>4, 8 consecutive patches
    {
        const int e = tid >> 4, i2 = tid & 15;
        const float g0v = g_g0[e];
        float v[8];
        float4 va = *(const float4*)&sY[e * SYP + i2 * 8];
        float4 vb = *(const float4*)&sY[e * SYP + i2 * 8 + 4];
        v[0] = va.x + g0v; v[1] = va.y + g0v; v[2] = va.z + g0v; v[3] = va.w + g0v;
        v[4] = vb.x + g0v; v[5] = vb.y + g0v; v[6] = vb.z + g0v; v[7] = vb.w + g0v;

        float s = 0.f, qq = 0.f;
#pragma unroll
        for (int j = 0; j < 8; j++) { s += v[j]; qq += v[j] * v[j]; }

        float* dst = &g_Y[(((size_t)(b * 16 + e)) << 14) + (hr << 7) + i2 * 8];
        *(float4*)dst = make_float4(v[0], v[1], v[2], v[3]);
        *(float4*)(dst + 4) = make_float4(v[4], v[5], v[6], v[7]);

#pragma unroll
        for (int off = 8; off; off >>= 1) {
            s  += __shfl_down_sync(0xffffffffu, s, off, 16);
            qq += __shfl_down_sync(0xffffffffu, qq, off, 16);
        }
        if (i2 == 0) {
            g_psum[(b * 16 + e) * 128 + hr] = s;
            g_psq[(b * 16 + e) * 128 + hr] = qq;
        }
    }
}

// ---------------------------------------------------------------------------
// Kernel 3: stats + per-channel scale/shift. 64 blocks x 128 threads.
// ---------------------------------------------------------------------------
__global__ void __launch_bounds__(128) stats_kernel(const float* __restrict__ gamma,
                                                    const float* __restrict__ beta) {
    __shared__ float ss[4], sq[4];
    const int bg = blockIdx.x;
    const int b = bg >> 3, grp = bg & 7;
    const int tid = threadIdx.x;
    const int base0 = (b * 16 + grp * 2) * 128;
    const int base1 = base0 + 128;
    float s = g_psum[base0 + tid] + g_psum[base1 + tid];
    float q = g_psq[base0 + tid]  + g_psq[base1 + tid];
#pragma unroll
    for (int off = 16; off; off >>= 1) {
        s += __shfl_down_sync(0xffffffffu, s, off);
        q += __shfl_down_sync(0xffffffffu, q, off);
    }
    const int lane = tid & 31, wrp = tid >> 5;
    if (lane == 0) { ss[wrp] = s; sq[wrp] = q; }
    __syncthreads();
    if (tid < 2) {
        float st = ss[0] + ss[1] + ss[2] + ss[3];
        float qt = sq[0] + sq[1] + sq[2] + sq[3];
        const float invN = 1.0f / 32768.0f;
        float mean = st * invN;
        float var  = qt * invN - mean * mean;
        float istd = rsqrtf(var + 1e-5f);
        const int e = grp * 2 + tid;
        float sc = istd * gamma[e];
        g_sc[b * 16 + e] = sc;
        g_sh[b * 16 + e] = beta[e] - mean * sc;
    }
}

// ---------------------------------------------------------------------------
// Kernel 4: normalize via table lookup. 524288 threads, one float4 each.
// ---------------------------------------------------------------------------
__global__ void __launch_bounds__(512) finalize_kernel(float* __restrict__ out) {
    const int idx = blockIdx.x * 512 + threadIdx.x;       // 524288 float4
    float4 v = ((const float4*)g_Y)[idx];
    const int plane = idx >> 12;                          // = b*16 + e
    const float sc = g_sc[plane];
    const float sh = g_sh[plane];
    v.x = v.x * sc + sh; v.y = v.y * sc + sh;
    v.z = v.z * sc + sh; v.w = v.w * sc + sh;
    ((float4*)out)[idx] = v;
}

extern "C" void kernel_launch(void* const* d_in, const int* in_sizes, int n_in,
                              void* d_out, int out_size) {
    const float* x     = (const float*)d_in[0];
    const float* wr    = (const float*)d_in[1];
    const float* wi    = (const float*)d_in[2];
    const float* br    = (const float*)d_in[3];
    const float* bi    = (const float*)d_in[4];
    const float* cw    = (const float*)d_in[5];
    const float* cb    = (const float*)d_in[6];
    const float* gamma = (const float*)d_in[7];
    const float* beta  = (const float*)d_in[8];
    float* out = (float*)d_out;

    precompute_kernel<<<16, 1024>>>(wr, wi, br, bi, cw, cb);
    main_kernel<<<1024, 256>>>(x);
    stats_kernel<<<64, 128>>>(gamma, beta);
    finalize_kernel<<<1024, 512>>>(out);
}